// round 1
// baseline (speedup 1.0000x reference)
#include <cuda_runtime.h>
#include <math.h>

#define T_TOK 2048
#define D 1024
#define DM 4096
#define E 8
#define CAP 2048

// ---- device scratch (static globals: allocation-guard safe) ----
__device__ int   g_cnt[E];
__device__ int   g_tok[E * CAP];
__device__ float g_wt [E * CAP];
__device__ float g_hid[(size_t)E * CAP * DM];   // 256 MB, only routed rows touched

// ---------------------------------------------------------------
__global__ void zero_cnt_kernel() {
    if (threadIdx.x < E) g_cnt[threadIdx.x] = 0;
}

// One block per token. Warp w computes logit for expert w, then thread 0
// does exact fp32 softmax + top-2 + renormalize (ties -> lower index, like
// jax.lax.top_k), and appends the token to both experts' gather lists.
__global__ void router_kernel(const float* __restrict__ x,
                              const float* __restrict__ Wg) {
    int t    = blockIdx.x;
    int lane = threadIdx.x & 31;
    int w    = threadIdx.x >> 5;     // 0..7
    const float* h = x + (size_t)t * D;

    float s = 0.f;
    for (int i = lane; i < D; i += 32)
        s += h[i] * Wg[i * E + w];
    #pragma unroll
    for (int o = 16; o; o >>= 1)
        s += __shfl_xor_sync(0xffffffffu, s, o);

    __shared__ float logits[E];
    if (lane == 0) logits[w] = s;
    __syncthreads();

    if (threadIdx.x == 0) {
        float m = -1e30f;
        #pragma unroll
        for (int e = 0; e < E; e++) m = fmaxf(m, logits[e]);
        float p[E];
        #pragma unroll
        for (int e = 0; e < E; e++) p[e] = expf(logits[e] - m);

        int e0 = 0;
        #pragma unroll
        for (int e = 1; e < E; e++) if (p[e] > p[e0]) e0 = e;
        int e1 = (e0 == 0) ? 1 : 0;
        #pragma unroll
        for (int e = 0; e < E; e++) {
            if (e == e0) continue;
            if (p[e] > p[e1]) e1 = e;
        }
        float rs = 1.f / (p[e0] + p[e1]);
        float w0 = p[e0] * rs;
        float w1 = p[e1] * rs;

        int i0 = atomicAdd(&g_cnt[e0], 1);
        g_tok[e0 * CAP + i0] = t;  g_wt[e0 * CAP + i0] = w0;
        int i1 = atomicAdd(&g_cnt[e1], 1);
        g_tok[e1 * CAP + i1] = t;  g_wt[e1 * CAP + i1] = w1;
    }
}

// ---------------------------------------------------------------
// Up-projection: for expert e (blockIdx.z), gathered token rows.
// hid[r, n] = silu(h_r . Wg_e[:, n]) * (h_r . Wi_e[:, n])
// Tile: BM=64 (tokens) x BN=128 (mlp cols) x BK=16. 256 threads, 4x8x2 regs.
__global__ void __launch_bounds__(256)
moe_up_kernel(const float* __restrict__ x,
              const float* __restrict__ Wgate,
              const float* __restrict__ Win) {
    int e   = blockIdx.z;
    int cnt = g_cnt[e];
    int row0 = blockIdx.x * 64;
    if (row0 >= cnt) return;
    int n0 = blockIdx.y * 128;

    __shared__ float As[64][20];     // [row][k], padded
    __shared__ float Bg[16][128];    // [k][n]
    __shared__ float Bi[16][128];

    int tid = threadIdx.x;

    // A loader: 4 threads per row, float4 each
    int ar   = tid >> 2;            // 0..63
    int ak   = (tid & 3) * 4;       // 0,4,8,12
    int arow = row0 + ar;
    bool aval = (arow < cnt);
    int tok  = aval ? g_tok[e * CAP + arow] : 0;
    const float* aptr = x + (size_t)tok * D + ak;

    // B loader: 16 k-rows x 128 n-cols, 2 float4 per thread per matrix
    int bk = tid >> 4;              // 0..15
    int bn = (tid & 15) * 8;        // 0..120
    const float* gptr = Wgate + (size_t)e * D * DM + (size_t)bk * DM + n0 + bn;
    const float* iptr = Win   + (size_t)e * D * DM + (size_t)bk * DM + n0 + bn;

    int ty = tid >> 4;              // 0..15  (rows ty, ty+16, ty+32, ty+48)
    int cb = tid & 15;              // cols cb + 16*j  (conflict-free LDS)

    float accg[4][8], acci[4][8];
    #pragma unroll
    for (int i = 0; i < 4; i++)
        #pragma unroll
        for (int j = 0; j < 8; j++) { accg[i][j] = 0.f; acci[i][j] = 0.f; }

    for (int k0 = 0; k0 < D; k0 += 16) {
        float4 av = aval ? *(const float4*)(aptr + k0) : make_float4(0,0,0,0);
        float4 gv0 = *(const float4*)(gptr + (size_t)k0 * DM);
        float4 gv1 = *(const float4*)(gptr + (size_t)k0 * DM + 4);
        float4 iv0 = *(const float4*)(iptr + (size_t)k0 * DM);
        float4 iv1 = *(const float4*)(iptr + (size_t)k0 * DM + 4);
        __syncthreads();
        *(float4*)&As[ar][ak]   = av;
        *(float4*)&Bg[bk][bn]   = gv0;  *(float4*)&Bg[bk][bn+4] = gv1;
        *(float4*)&Bi[bk][bn]   = iv0;  *(float4*)&Bi[bk][bn+4] = iv1;
        __syncthreads();

        #pragma unroll
        for (int kk = 0; kk < 16; kk++) {
            float a[4];
            #pragma unroll
            for (int i = 0; i < 4; i++) a[i] = As[ty + 16*i][kk];
            #pragma unroll
            for (int j = 0; j < 8; j++) {
                float bgv = Bg[kk][cb + 16*j];
                float biv = Bi[kk][cb + 16*j];
                #pragma unroll
                for (int i = 0; i < 4; i++) {
                    accg[i][j] = fmaf(a[i], bgv, accg[i][j]);
                    acci[i][j] = fmaf(a[i], biv, acci[i][j]);
                }
            }
        }
    }

    #pragma unroll
    for (int i = 0; i < 4; i++) {
        int r = row0 + ty + 16*i;
        if (r >= cnt) continue;
        float* hrow = g_hid + (size_t)(e * CAP + r) * DM + n0;
        #pragma unroll
        for (int j = 0; j < 8; j++) {
            float gv = accg[i][j];
            float s  = gv / (1.f + __expf(-gv));   // silu
            hrow[cb + 16*j] = s * acci[i][j];
        }
    }
}

// ---------------------------------------------------------------
// Down-projection + weighted scatter-add.
// out[tok_r, n] += w_r * (hid_r . Wo_e[:, n])
__global__ void __launch_bounds__(256)
moe_down_kernel(const float* __restrict__ Wout,
                float* __restrict__ out) {
    int e   = blockIdx.z;
    int cnt = g_cnt[e];
    int row0 = blockIdx.x * 64;
    if (row0 >= cnt) return;
    int n0 = blockIdx.y * 128;

    __shared__ float As[64][20];
    __shared__ float Bs[16][128];

    int tid = threadIdx.x;
    int ar   = tid >> 2;
    int ak   = (tid & 3) * 4;
    int arow = row0 + ar;
    bool aval = (arow < cnt);
    const float* aptr = g_hid + (size_t)(e * CAP + (aval ? arow : 0)) * DM + ak;

    int bk = tid >> 4;
    int bn = (tid & 15) * 8;
    const float* bptr = Wout + (size_t)e * DM * D + (size_t)bk * D + n0 + bn;

    int ty = tid >> 4;
    int cb = tid & 15;

    float acc[4][8];
    #pragma unroll
    for (int i = 0; i < 4; i++)
        #pragma unroll
        for (int j = 0; j < 8; j++) acc[i][j] = 0.f;

    for (int k0 = 0; k0 < DM; k0 += 16) {
        float4 av = aval ? *(const float4*)(aptr + k0) : make_float4(0,0,0,0);
        float4 bv0 = *(const float4*)(bptr + (size_t)k0 * D);
        float4 bv1 = *(const float4*)(bptr + (size_t)k0 * D + 4);
        __syncthreads();
        *(float4*)&As[ar][ak] = av;
        *(float4*)&Bs[bk][bn]   = bv0;
        *(float4*)&Bs[bk][bn+4] = bv1;
        __syncthreads();

        #pragma unroll
        for (int kk = 0; kk < 16; kk++) {
            float a[4];
            #pragma unroll
            for (int i = 0; i < 4; i++) a[i] = As[ty + 16*i][kk];
            #pragma unroll
            for (int j = 0; j < 8; j++) {
                float b = Bs[kk][cb + 16*j];
                #pragma unroll
                for (int i = 0; i < 4; i++)
                    acc[i][j] = fmaf(a[i], b, acc[i][j]);
            }
        }
    }

    #pragma unroll
    for (int i = 0; i < 4; i++) {
        int r = row0 + ty + 16*i;
        if (r >= cnt) continue;
        int   tok = g_tok[e * CAP + r];
        float w   = g_wt [e * CAP + r];
        float* orow = out + (size_t)tok * D + n0;
        #pragma unroll
        for (int j = 0; j < 8; j++)
            atomicAdd(&orow[cb + 16*j], acc[i][j] * w);
    }
}

// ---------------------------------------------------------------
extern "C" void kernel_launch(void* const* d_in, const int* in_sizes, int n_in,
                              void* d_out, int out_size) {
    const float* x    = (const float*)d_in[0];   // [1,2048,1024]
    const float* Wg   = (const float*)d_in[1];   // [1024,8]
    const float* Weg  = (const float*)d_in[2];   // [8,1024,4096]
    const float* Wei  = (const float*)d_in[3];   // [8,1024,4096]
    const float* Weo  = (const float*)d_in[4];   // [8,4096,1024]
    float* out = (float*)d_out;                  // [1,2048,1024]

    cudaMemsetAsync(out, 0, (size_t)out_size * sizeof(float));
    zero_cnt_kernel<<<1, 32>>>();
    router_kernel<<<T_TOK, 256>>>(x, Wg);
    moe_up_kernel  <<<dim3(CAP/64, DM/128, E), 256>>>(x, Weg, Wei);
    moe_down_kernel<<<dim3(CAP/64, D /128, E), 256>>>(Weo, out);
}

// round 3
// speedup vs baseline: 2.9526x; 2.9526x over previous
#include <cuda_runtime.h>
#include <cuda_bf16.h>
#include <math.h>
#include <stdint.h>

#define T_TOK 2048
#define D     1024
#define DM    4096
#define E     8
#define CAP   2048

// ---------------- device scratch (static: allocation-guard safe) ----------------
__device__ int   g_cnt[E];
__device__ int   g_tok[E * CAP];
__device__ float g_wt [E * CAP];
__device__ __nv_bfloat16 g_xhi[T_TOK * D];
__device__ __nv_bfloat16 g_xlo[T_TOK * D];
__device__ __nv_bfloat16 g_hhi[(size_t)E * CAP * DM];   // 128 MB
__device__ __nv_bfloat16 g_hlo[(size_t)E * CAP * DM];   // 128 MB

// ---------------- helpers ----------------
__device__ __forceinline__ uint32_t smem_u32(const void* p) {
    uint32_t a;
    asm("{ .reg .u64 t; cvta.to.shared.u64 t, %1; cvt.u32.u64 %0, t; }" : "=r"(a) : "l"(p));
    return a;
}
__device__ __forceinline__ void split2(float v, __nv_bfloat16& h, __nv_bfloat16& l) {
    h = __float2bfloat16(v);
    l = __float2bfloat16(v - __bfloat162float(h));
}
__device__ __forceinline__ uint32_t packbf(__nv_bfloat16 a, __nv_bfloat16 b) {
    __nv_bfloat162 t = __halves2bfloat162(a, b);
    return *reinterpret_cast<uint32_t*>(&t);
}
// convert 8 fp32 -> 8 bf16 hi + 8 bf16 lo (packed as uint4 each)
__device__ __forceinline__ void cv8(float4 a, float4 b, uint4& uh, uint4& ul) {
    __nv_bfloat16 h0, l0, h1, l1, h2, l2, h3, l3;
    split2(a.x, h0, l0); split2(a.y, h1, l1); split2(a.z, h2, l2); split2(a.w, h3, l3);
    uh.x = packbf(h0, h1); uh.y = packbf(h2, h3);
    ul.x = packbf(l0, l1); ul.y = packbf(l2, l3);
    split2(b.x, h0, l0); split2(b.y, h1, l1); split2(b.z, h2, l2); split2(b.w, h3, l3);
    uh.z = packbf(h0, h1); uh.w = packbf(h2, h3);
    ul.z = packbf(l0, l1); ul.w = packbf(l2, l3);
}
__device__ __forceinline__ void ldsm4(uint32_t (&r)[4], uint32_t addr) {
    asm volatile("ldmatrix.sync.aligned.m8n8.x4.shared.b16 {%0,%1,%2,%3}, [%4];"
        : "=r"(r[0]), "=r"(r[1]), "=r"(r[2]), "=r"(r[3]) : "r"(addr));
}
__device__ __forceinline__ void ldsm4t(uint32_t (&r)[4], uint32_t addr) {
    asm volatile("ldmatrix.sync.aligned.m8n8.x4.trans.shared.b16 {%0,%1,%2,%3}, [%4];"
        : "=r"(r[0]), "=r"(r[1]), "=r"(r[2]), "=r"(r[3]) : "r"(addr));
}
__device__ __forceinline__ void mma16816(float* d, const uint32_t (&a)[4],
                                         uint32_t b0, uint32_t b1) {
    asm volatile(
        "mma.sync.aligned.m16n8k16.row.col.f32.bf16.bf16.f32 "
        "{%0,%1,%2,%3}, {%4,%5,%6,%7}, {%8,%9}, {%0,%1,%2,%3};"
        : "+f"(d[0]), "+f"(d[1]), "+f"(d[2]), "+f"(d[3])
        : "r"(a[0]), "r"(a[1]), "r"(a[2]), "r"(a[3]), "r"(b0), "r"(b1));
}

// ---------------------------------------------------------------
__global__ void zero_cnt_kernel() {
    if (threadIdx.x < E) g_cnt[threadIdx.x] = 0;
}

__global__ void convert_x_kernel(const float4* __restrict__ x4) {
    int i = blockIdx.x * blockDim.x + threadIdx.x;   // < T_TOK*D/4
    float4 v = x4[i];
    __nv_bfloat16 h0, h1, h2, h3, l0, l1, l2, l3;
    split2(v.x, h0, l0); split2(v.y, h1, l1);
    split2(v.z, h2, l2); split2(v.w, h3, l3);
    ((uint2*)g_xhi)[i] = make_uint2(packbf(h0, h1), packbf(h2, h3));
    ((uint2*)g_xlo)[i] = make_uint2(packbf(l0, l1), packbf(l2, l3));
}

__global__ void router_kernel(const float* __restrict__ x,
                              const float* __restrict__ Wg) {
    int t = blockIdx.x;
    int lane = threadIdx.x & 31;
    int w = threadIdx.x >> 5;
    const float* h = x + (size_t)t * D;
    float s = 0.f;
    for (int i = lane; i < D; i += 32) s += h[i] * Wg[i * E + w];
    #pragma unroll
    for (int o = 16; o; o >>= 1) s += __shfl_xor_sync(0xffffffffu, s, o);
    __shared__ float logits[E];
    if (lane == 0) logits[w] = s;
    __syncthreads();
    if (threadIdx.x == 0) {
        float m = -1e30f;
        #pragma unroll
        for (int e = 0; e < E; e++) m = fmaxf(m, logits[e]);
        float p[E];
        #pragma unroll
        for (int e = 0; e < E; e++) p[e] = expf(logits[e] - m);
        int e0 = 0;
        #pragma unroll
        for (int e = 1; e < E; e++) if (p[e] > p[e0]) e0 = e;
        int e1 = (e0 == 0) ? 1 : 0;
        #pragma unroll
        for (int e = 0; e < E; e++) { if (e == e0) continue; if (p[e] > p[e1]) e1 = e; }
        float rs = 1.f / (p[e0] + p[e1]);
        int i0 = atomicAdd(&g_cnt[e0], 1);
        g_tok[e0 * CAP + i0] = t;  g_wt[e0 * CAP + i0] = p[e0] * rs;
        int i1 = atomicAdd(&g_cnt[e1], 1);
        g_tok[e1 * CAP + i1] = t;  g_wt[e1 * CAP + i1] = p[e1] * rs;
    }
}

// ---------------------------------------------------------------
// Up-proj: hid = silu(X@Wg) * (X@Wi). Block tile 128(tok) x 64(n) x K=1024.
// A strides 80B/row (conflict-free ldmatrix), B strides 144B/row.
__global__ void __launch_bounds__(256)
moe_up_kernel(const float* __restrict__ Wgate, const float* __restrict__ Win) {
    __shared__ __align__(16) char sAh[128 * 80];
    __shared__ __align__(16) char sAl[128 * 80];
    __shared__ __align__(16) char sGh[32 * 144];
    __shared__ __align__(16) char sGl[32 * 144];
    __shared__ __align__(16) char sIh[32 * 144];
    __shared__ __align__(16) char sIl[32 * 144];

    int e = blockIdx.z;
    int cnt = g_cnt[e];
    int row0 = blockIdx.x * 128;
    if (row0 >= cnt) return;
    int n0 = blockIdx.y * 64;

    int tid = threadIdx.x, wid = tid >> 5, lane = tid & 31;
    int warp_m = wid >> 1, warp_n = wid & 1;

    // ---- A loader: one row, two 16B quarters ----
    int rA = tid >> 1;
    int q0 = (tid & 1) * 2;           // quarter index 0 or 2
    int tok = g_tok[e * CAP + min(row0 + rA, cnt - 1)];
    const uint4* pAh = (const uint4*)(g_xhi + (size_t)tok * D);
    const uint4* pAl = (const uint4*)(g_xlo + (size_t)tok * D);
    uint32_t sAoff = rA * 80 + q0 * 16;

    // ---- B loader: k=tid>>3, n8=(tid&7)*8 ----
    int bk = tid >> 3;
    int bn = (tid & 7) * 8;
    const float* pG = Wgate + (size_t)e * D * DM + (size_t)bk * DM + n0 + bn;
    const float* pI = Win   + (size_t)e * D * DM + (size_t)bk * DM + n0 + bn;
    uint32_t sBoff = bk * 144 + bn * 2;

    // ---- compute addresses ----
    uint32_t aH = smem_u32(sAh) + (warp_m * 32 + (lane & 15)) * 80 + (lane >> 4) * 16;
    uint32_t aL = smem_u32(sAl) + (warp_m * 32 + (lane & 15)) * 80 + (lane >> 4) * 16;
    uint32_t bcol = (warp_n * 32 + (lane >> 4) * 8) * 2;
    uint32_t gH = smem_u32(sGh) + (lane & 15) * 144 + bcol;
    uint32_t gL = smem_u32(sGl) + (lane & 15) * 144 + bcol;
    uint32_t iH = smem_u32(sIh) + (lane & 15) * 144 + bcol;
    uint32_t iL = smem_u32(sIl) + (lane & 15) * 144 + bcol;

    float aG[2][4][4], aI[2][4][4];
    #pragma unroll
    for (int i = 0; i < 2; i++)
        #pragma unroll
        for (int j = 0; j < 4; j++)
            #pragma unroll
            for (int k = 0; k < 4; k++) { aG[i][j][k] = 0.f; aI[i][j][k] = 0.f; }

    const int NIT = D / 32;
    uint4 ra0, ra1, rl0, rl1;
    float4 vg0, vg1, vi0, vi1;
    // prefetch it=0
    ra0 = pAh[q0]; ra1 = pAh[q0 + 1]; rl0 = pAl[q0]; rl1 = pAl[q0 + 1];
    vg0 = *(const float4*)pG; vg1 = *(const float4*)(pG + 4);
    vi0 = *(const float4*)pI; vi1 = *(const float4*)(pI + 4);

    for (int it = 0; it < NIT; ++it) {
        __syncthreads();
        *(uint4*)(sAh + sAoff) = ra0;  *(uint4*)(sAh + sAoff + 16) = ra1;
        *(uint4*)(sAl + sAoff) = rl0;  *(uint4*)(sAl + sAoff + 16) = rl1;
        uint4 uh, ul;
        cv8(vg0, vg1, uh, ul);
        *(uint4*)(sGh + sBoff) = uh;  *(uint4*)(sGl + sBoff) = ul;
        cv8(vi0, vi1, uh, ul);
        *(uint4*)(sIh + sBoff) = uh;  *(uint4*)(sIl + sBoff) = ul;
        __syncthreads();

        if (it + 1 < NIT) {
            int b = (it + 1) * 4;
            ra0 = pAh[b + q0]; ra1 = pAh[b + q0 + 1];
            rl0 = pAl[b + q0]; rl1 = pAl[b + q0 + 1];
            const float* g = pG + (size_t)(it + 1) * 32 * DM;
            const float* ii = pI + (size_t)(it + 1) * 32 * DM;
            vg0 = *(const float4*)g;  vg1 = *(const float4*)(g + 4);
            vi0 = *(const float4*)ii; vi1 = *(const float4*)(ii + 4);
        }

        #pragma unroll
        for (int kk = 0; kk < 32; kk += 16) {
            uint32_t A0h[4], A1h[4], A0l[4], A1l[4];
            ldsm4(A0h, aH + kk * 2);          ldsm4(A1h, aH + kk * 2 + 1280);
            ldsm4(A0l, aL + kk * 2);          ldsm4(A1l, aL + kk * 2 + 1280);
            #pragma unroll
            for (int jj = 0; jj < 2; jj++) {
                uint32_t bh[4], bl[4];
                ldsm4t(bh, gH + kk * 144 + jj * 32);
                ldsm4t(bl, gL + kk * 144 + jj * 32);
                mma16816(aG[0][2*jj],   A0h, bh[0], bh[1]);
                mma16816(aG[0][2*jj+1], A0h, bh[2], bh[3]);
                mma16816(aG[1][2*jj],   A1h, bh[0], bh[1]);
                mma16816(aG[1][2*jj+1], A1h, bh[2], bh[3]);
                mma16816(aG[0][2*jj],   A0h, bl[0], bl[1]);
                mma16816(aG[0][2*jj+1], A0h, bl[2], bl[3]);
                mma16816(aG[1][2*jj],   A1h, bl[0], bl[1]);
                mma16816(aG[1][2*jj+1], A1h, bl[2], bl[3]);
                mma16816(aG[0][2*jj],   A0l, bh[0], bh[1]);
                mma16816(aG[0][2*jj+1], A0l, bh[2], bh[3]);
                mma16816(aG[1][2*jj],   A1l, bh[0], bh[1]);
                mma16816(aG[1][2*jj+1], A1l, bh[2], bh[3]);

                ldsm4t(bh, iH + kk * 144 + jj * 32);
                ldsm4t(bl, iL + kk * 144 + jj * 32);
                mma16816(aI[0][2*jj],   A0h, bh[0], bh[1]);
                mma16816(aI[0][2*jj+1], A0h, bh[2], bh[3]);
                mma16816(aI[1][2*jj],   A1h, bh[0], bh[1]);
                mma16816(aI[1][2*jj+1], A1h, bh[2], bh[3]);
                mma16816(aI[0][2*jj],   A0h, bl[0], bl[1]);
                mma16816(aI[0][2*jj+1], A0h, bl[2], bl[3]);
                mma16816(aI[1][2*jj],   A1h, bl[0], bl[1]);
                mma16816(aI[1][2*jj+1], A1h, bl[2], bl[3]);
                mma16816(aI[0][2*jj],   A0l, bh[0], bh[1]);
                mma16816(aI[0][2*jj+1], A0l, bh[2], bh[3]);
                mma16816(aI[1][2*jj],   A1l, bh[0], bh[1]);
                mma16816(aI[1][2*jj+1], A1l, bh[2], bh[3]);
            }
        }
    }

    // epilogue: silu(g)*i -> split bf16 -> g_hhi/g_hlo
    int lr = warp_m * 32 + (lane >> 2);
    int cbase = n0 + warp_n * 32 + (lane & 3) * 2;
    #pragma unroll
    for (int i = 0; i < 2; i++) {
        #pragma unroll
        for (int h = 0; h < 2; h++) {
            int gr = row0 + lr + i * 16 + h * 8;
            if (gr >= cnt) continue;
            size_t base = (size_t)(e * CAP + gr) * DM;
            #pragma unroll
            for (int jn = 0; jn < 4; jn++) {
                float gg0 = aG[i][jn][2*h], gg1 = aG[i][jn][2*h+1];
                float ii0 = aI[i][jn][2*h], ii1 = aI[i][jn][2*h+1];
                float v0 = (gg0 / (1.f + expf(-gg0))) * ii0;
                float v1 = (gg1 / (1.f + expf(-gg1))) * ii1;
                __nv_bfloat16 h0, l0, h1, l1;
                split2(v0, h0, l0); split2(v1, h1, l1);
                *(uint32_t*)(g_hhi + base + cbase + jn * 8) = packbf(h0, h1);
                *(uint32_t*)(g_hlo + base + cbase + jn * 8) = packbf(l0, l1);
            }
        }
    }
}

// ---------------------------------------------------------------
// Down-proj + weighted scatter: out[tok] += w * (hid @ Wout). K = 4096.
__global__ void __launch_bounds__(256)
moe_dn_kernel(const float* __restrict__ Wout, float* __restrict__ out) {
    __shared__ __align__(16) char sAh[128 * 80];
    __shared__ __align__(16) char sAl[128 * 80];
    __shared__ __align__(16) char sBh[32 * 144];
    __shared__ __align__(16) char sBl[32 * 144];

    int e = blockIdx.z;
    int cnt = g_cnt[e];
    int row0 = blockIdx.x * 128;
    if (row0 >= cnt) return;
    int n0 = blockIdx.y * 64;

    int tid = threadIdx.x, wid = tid >> 5, lane = tid & 31;
    int warp_m = wid >> 1, warp_n = wid & 1;

    int rA = tid >> 1;
    int q0 = (tid & 1) * 2;
    int rowc = min(row0 + rA, cnt - 1);
    const uint4* pAh = (const uint4*)(g_hhi + (size_t)(e * CAP + rowc) * DM);
    const uint4* pAl = (const uint4*)(g_hlo + (size_t)(e * CAP + rowc) * DM);
    uint32_t sAoff = rA * 80 + q0 * 16;

    int bk = tid >> 3;
    int bn = (tid & 7) * 8;
    const float* pB = Wout + (size_t)e * DM * D + (size_t)bk * D + n0 + bn;
    uint32_t sBoff = bk * 144 + bn * 2;

    uint32_t aH = smem_u32(sAh) + (warp_m * 32 + (lane & 15)) * 80 + (lane >> 4) * 16;
    uint32_t aL = smem_u32(sAl) + (warp_m * 32 + (lane & 15)) * 80 + (lane >> 4) * 16;
    uint32_t bcol = (warp_n * 32 + (lane >> 4) * 8) * 2;
    uint32_t bH = smem_u32(sBh) + (lane & 15) * 144 + bcol;
    uint32_t bL = smem_u32(sBl) + (lane & 15) * 144 + bcol;

    float acc[2][4][4];
    #pragma unroll
    for (int i = 0; i < 2; i++)
        #pragma unroll
        for (int j = 0; j < 4; j++)
            #pragma unroll
            for (int k = 0; k < 4; k++) acc[i][j][k] = 0.f;

    const int NIT = DM / 32;   // 128
    uint4 ra0, ra1, rl0, rl1;
    float4 vb0, vb1;
    ra0 = pAh[q0]; ra1 = pAh[q0 + 1]; rl0 = pAl[q0]; rl1 = pAl[q0 + 1];
    vb0 = *(const float4*)pB; vb1 = *(const float4*)(pB + 4);

    for (int it = 0; it < NIT; ++it) {
        __syncthreads();
        *(uint4*)(sAh + sAoff) = ra0;  *(uint4*)(sAh + sAoff + 16) = ra1;
        *(uint4*)(sAl + sAoff) = rl0;  *(uint4*)(sAl + sAoff + 16) = rl1;
        uint4 uh, ul;
        cv8(vb0, vb1, uh, ul);
        *(uint4*)(sBh + sBoff) = uh;  *(uint4*)(sBl + sBoff) = ul;
        __syncthreads();

        if (it + 1 < NIT) {
            int b = (it + 1) * 4;
            ra0 = pAh[b + q0]; ra1 = pAh[b + q0 + 1];
            rl0 = pAl[b + q0]; rl1 = pAl[b + q0 + 1];
            const float* w = pB + (size_t)(it + 1) * 32 * D;
            vb0 = *(const float4*)w; vb1 = *(const float4*)(w + 4);
        }

        #pragma unroll
        for (int kk = 0; kk < 32; kk += 16) {
            uint32_t A0h[4], A1h[4], A0l[4], A1l[4];
            ldsm4(A0h, aH + kk * 2);          ldsm4(A1h, aH + kk * 2 + 1280);
            ldsm4(A0l, aL + kk * 2);          ldsm4(A1l, aL + kk * 2 + 1280);
            #pragma unroll
            for (int jj = 0; jj < 2; jj++) {
                uint32_t bh[4], bl[4];
                ldsm4t(bh, bH + kk * 144 + jj * 32);
                ldsm4t(bl, bL + kk * 144 + jj * 32);
                mma16816(acc[0][2*jj],   A0h, bh[0], bh[1]);
                mma16816(acc[0][2*jj+1], A0h, bh[2], bh[3]);
                mma16816(acc[1][2*jj],   A1h, bh[0], bh[1]);
                mma16816(acc[1][2*jj+1], A1h, bh[2], bh[3]);
                mma16816(acc[0][2*jj],   A0h, bl[0], bl[1]);
                mma16816(acc[0][2*jj+1], A0h, bl[2], bl[3]);
                mma16816(acc[1][2*jj],   A1h, bl[0], bl[1]);
                mma16816(acc[1][2*jj+1], A1h, bl[2], bl[3]);
                mma16816(acc[0][2*jj],   A0l, bh[0], bh[1]);
                mma16816(acc[0][2*jj+1], A0l, bh[2], bh[3]);
                mma16816(acc[1][2*jj],   A1l, bh[0], bh[1]);
                mma16816(acc[1][2*jj+1], A1l, bh[2], bh[3]);
            }
        }
    }

    int lr = warp_m * 32 + (lane >> 2);
    int cbase = n0 + warp_n * 32 + (lane & 3) * 2;
    #pragma unroll
    for (int i = 0; i < 2; i++) {
        #pragma unroll
        for (int h = 0; h < 2; h++) {
            int gr = row0 + lr + i * 16 + h * 8;
            if (gr >= cnt) continue;
            int   tk = g_tok[e * CAP + gr];
            float wt = g_wt [e * CAP + gr];
            float* po = out + (size_t)tk * D;
            #pragma unroll
            for (int jn = 0; jn < 4; jn++) {
                atomicAdd(po + cbase + jn * 8,     acc[i][jn][2*h]     * wt);
                atomicAdd(po + cbase + jn * 8 + 1, acc[i][jn][2*h + 1] * wt);
            }
        }
    }
}

// ---------------------------------------------------------------
extern "C" void kernel_launch(void* const* d_in, const int* in_sizes, int n_in,
                              void* d_out, int out_size) {
    const float* x   = (const float*)d_in[0];
    const float* Wg  = (const float*)d_in[1];
    const float* Weg = (const float*)d_in[2];
    const float* Wei = (const float*)d_in[3];
    const float* Weo = (const float*)d_in[4];
    float* out = (float*)d_out;

    cudaMemsetAsync(out, 0, (size_t)out_size * sizeof(float));
    zero_cnt_kernel<<<1, 32>>>();
    convert_x_kernel<<<(T_TOK * D / 4) / 256, 256>>>((const float4*)x);
    router_kernel<<<T_TOK, 256>>>(x, Wg);
    moe_up_kernel<<<dim3(CAP / 128, DM / 64, E), 256>>>(Weg, Wei);
    moe_dn_kernel<<<dim3(CAP / 128, D / 64, E), 256>>>(Weo, out);
}